// round 15
// baseline (speedup 1.0000x reference)
#include <cuda_runtime.h>
#include <cuda_fp16.h>
#include <stdint.h>
#include <math.h>

#define NNODES  1000000
#define HID     256
#define HHALF   128
#define NGRAPH  1024

// ---- scratch (no allocations allowed) ----
__device__ float  g_scores[NNODES];
__device__ float  g_segmax[NGRAPH];
__device__ float  g_segsum[NGRAPH];
__device__ __half g_wh[HHALF * HID];   // w1 fp16, [n][k] row-major

__device__ __forceinline__ void atomicMaxF(float* addr, float v) {
    if (v >= 0.0f) atomicMax((int*)addr, __float_as_int(v));
    else           atomicMin((unsigned int*)addr, __float_as_uint(v));
}
__device__ __forceinline__ float tanh_fast(float x) {
    float y; asm("tanh.approx.f32 %0, %1;" : "=f"(y) : "f"(x)); return y;
}
__device__ __forceinline__ uint32_t smem_u32(const void* p) {
    uint32_t a;
    asm("{ .reg .u64 t; cvta.to.shared.u64 t, %1; cvt.u32.u64 %0, t; }"
        : "=r"(a) : "l"(p));
    return a;
}

#define MMA_F16(c, a, b0, b1)                                               \
    asm volatile("mma.sync.aligned.m16n8k16.row.col.f32.f16.f16.f32 "       \
                 "{%0,%1,%2,%3}, {%4,%5,%6,%7}, {%8,%9}, {%0,%1,%2,%3};"    \
                 : "+f"(c[0]), "+f"(c[1]), "+f"(c[2]), "+f"(c[3])           \
                 : "r"(a[0]), "r"(a[1]), "r"(a[2]), "r"(a[3]),              \
                   "r"(b0), "r"(b1))

#define LDSM4(r0, r1, r2, r3, addr)                                         \
    asm volatile("ldmatrix.sync.aligned.m8n8.x4.shared.b16 {%0,%1,%2,%3}, [%4];" \
                 : "=r"(r0), "=r"(r1), "=r"(r2), "=r"(r3) : "r"(addr))

__device__ __forceinline__ uint32_t f2h2(float2 v) {
    __half2 h = __floats2half2_rn(v.x, v.y);
    return *(uint32_t*)&h;
}

// ---------------------------------------------------------------------------
// K0: init per-graph reductions AND zero the output (k_pool atomicAdds into it)
// ---------------------------------------------------------------------------
__global__ void k_init(float* __restrict__ out) {
    int i = blockIdx.x * blockDim.x + threadIdx.x;
    if (i < NGRAPH) { g_segmax[i] = -INFINITY; g_segsum[i] = 0.0f; }
    if (i < NGRAPH * HID) out[i] = 0.0f;
}

// w1 [k][n] -> g_wh [n][k] fp16 RN
__global__ void k_prep(const float* __restrict__ w1) {
    int i = blockIdx.x * blockDim.x + threadIdx.x;
    if (i < HID * HHALF) {
        int k = i >> 7, nn = i & 127;
        g_wh[nn * HID + k] = __float2half_rn(w1[i]);
    }
}

// ---------------------------------------------------------------------------
// K1: warp-pair N-split GEMM. Tile = 64 rows; 8 warps = 4 row-groups x 2
// N-halves. Each warp: 16 rows x 64 N -> acc 32 regs -> 3 CTAs/SM (24 warps).
// A loaded from global straight into fragments with 2-DEEP prefetch; B fp16
// resident in SMEM via ldmatrix. One s_red barrier pair per tile.
// ---------------------------------------------------------------------------
#define TMS  64                      // rows per CTA tile
#define SPH  72                      // half stride: ldmatrix conflict-free
#define W_F  (HHALF * SPH)           // halves per 64-wide k chunk tile
#define NCH  4
#define SC_SMEM (NCH * W_F * 2 + (128 + 128 + 128) * 4)   // 75264 B -> 3 CTA/SM

__global__ __launch_bounds__(256, 3) void k_scores(
    const float* __restrict__ x,
    const int* __restrict__ batch,
    const float* __restrict__ b1,
    const float* __restrict__ w2,
    const float* __restrict__ b2,
    int n, int ntiles)
{
    extern __shared__ __half smh[];
    __half* ws    = smh;                       // [NCH][W_F]
    float*  s_b1  = (float*)(smh + NCH * W_F);
    float*  s_w2  = s_b1 + 128;
    float*  s_red = s_w2 + 128;                // [2][64]

    const int tid  = threadIdx.x;
    const int lane = tid & 31;
    const int warp = tid >> 5;
    const int rg   = warp >> 1;      // row group 0..3 (16 rows each)
    const int nh   = warp & 1;       // N half 0..1 (64 cols each)
    const int g    = lane >> 2;      // 0..7
    const int tq   = lane & 3;       // 0..3

    if (tid < HHALF) { s_b1[tid] = b1[tid]; s_w2[tid] = w2[tid]; }

    // ---- preload w into SMEM once (4096 uint4 = 16/thread) ----
#pragma unroll 4
    for (int i = tid; i < HHALF * HID / 8; i += 256) {
        int nn  = i >> 5;            // 32 uint4 per n-row
        int kb8 = (i & 31) * 8;      // k: 0,8,..248
        int c   = kb8 >> 6;          // chunk of 64
        int ko  = kb8 & 63;
        *(uint4*)&ws[c * W_F + nn * SPH + ko] =
            *(const uint4*)&g_wh[nn * HID + kb8];
    }
    __syncthreads();

    // B ldmatrix per-lane base (this warp's N half, chunk 0, ks 0, p = 0)
    const uint32_t ws_b = smem_u32(ws);
    const uint32_t b_base = ws_b +
        (uint32_t)(((nh * 64 + (lane & 7) + ((lane >> 4) & 1) * 8) * SPH
                    + ((lane >> 3) & 1) * 8) * 2);

    const float b2v  = b2[0];
    const int   koff = tq * 2;
    const float2 z2  = make_float2(0.f, 0.f);

    for (int t = blockIdx.x; t < ntiles; t += gridDim.x) {
        const int rowA = t * TMS + rg * 16 + g;
        const int rowB = rowA + 8;
        const bool vA = rowA < n, vB = rowB < n;
        const float* pA = x + (size_t)(vA ? rowA : 0) * HID + koff;
        const float* pB = x + (size_t)(vB ? rowB : 0) * HID + koff;

        float acc[8][4];
#pragma unroll
        for (int j = 0; j < 8; j++)
#pragma unroll
            for (int c = 0; c < 4; c++) acc[j][c] = 0.0f;

        // 2-deep prefetch stages
        float2 s[2][4];
#pragma unroll
        for (int st = 0; st < 2; st++) {
            const int kb = st * 16;
            s[st][0] = vA ? *(const float2*)(pA + kb)     : z2;
            s[st][1] = vB ? *(const float2*)(pB + kb)     : z2;
            s[st][2] = vA ? *(const float2*)(pA + kb + 8) : z2;
            s[st][3] = vB ? *(const float2*)(pB + kb + 8) : z2;
        }

#pragma unroll
        for (int ks = 0; ks < 16; ks++) {
            const int cur = ks & 1;
            uint32_t fa[4];
            fa[0] = f2h2(s[cur][0]); fa[1] = f2h2(s[cur][1]);
            fa[2] = f2h2(s[cur][2]); fa[3] = f2h2(s[cur][3]);
            // refill this stage with ks+2 (two iterations of cover)
            if (ks < 14) {
                const int kb = (ks + 2) * 16;
                s[cur][0] = vA ? *(const float2*)(pA + kb)     : z2;
                s[cur][1] = vB ? *(const float2*)(pB + kb)     : z2;
                s[cur][2] = vA ? *(const float2*)(pA + kb + 8) : z2;
                s[cur][3] = vB ? *(const float2*)(pB + kb + 8) : z2;
            }
            const uint32_t bb = b_base
                + (uint32_t)((ks >> 2) * (W_F * 2) + (ks & 3) * 32);
#pragma unroll
            for (int p = 0; p < 4; p++) {
                uint32_t B0, B1, B2, B3;
                LDSM4(B0, B1, B2, B3, bb + p * (16 * SPH * 2));
                MMA_F16(acc[p * 2 + 0], fa, B0, B1);
                MMA_F16(acc[p * 2 + 1], fa, B2, B3);
            }
        }

        // ---- epilogue: tanh + dot(w2) over this warp's 64 cols ----
        float sA = 0.0f, sB = 0.0f;
#pragma unroll
        for (int j = 0; j < 8; j++) {
            int n0 = nh * 64 + j * 8 + tq * 2;
            float b1a = s_b1[n0], b1b = s_b1[n0 + 1];
            float w2a = s_w2[n0], w2b = s_w2[n0 + 1];
            sA += tanh_fast(acc[j][0] + b1a) * w2a
                + tanh_fast(acc[j][1] + b1b) * w2b;
            sB += tanh_fast(acc[j][2] + b1a) * w2a
                + tanh_fast(acc[j][3] + b1b) * w2b;
        }
        sA += __shfl_xor_sync(0xffffffffu, sA, 1);
        sA += __shfl_xor_sync(0xffffffffu, sA, 2);
        sB += __shfl_xor_sync(0xffffffffu, sB, 1);
        sB += __shfl_xor_sync(0xffffffffu, sB, 2);
        if (tq == 0) {
            s_red[nh * 64 + rg * 16 + g]     = sA;
            s_red[nh * 64 + rg * 16 + g + 8] = sB;
        }
        __syncthreads();

        if (tid < TMS) {
            int node = t * TMS + tid;
            if (node < n) {
                float sc = s_red[tid] + s_red[64 + tid] + b2v;
                g_scores[node] = sc;
                int gg = batch[node];
                if (gg >= 0 && gg < NGRAPH) atomicMaxF(&g_segmax[gg], sc);
            }
        }
        __syncthreads();   // protect s_red before next tile
    }
}

// ---------------------------------------------------------------------------
// K2: e = exp(score - segmax[g]); segment-sum with warp aggregation.
// ---------------------------------------------------------------------------
__global__ void k_expsum(const int* __restrict__ batch, int n)
{
    int i = blockIdx.x * blockDim.x + threadIdx.x;
    bool valid = (i < n);
    int g = valid ? batch[i] : -1;
    if (g < 0 || g >= NGRAPH) g = -1;
    float e = 0.0f;
    if (valid && g >= 0) {
        e = expf(g_scores[i] - g_segmax[g]);
        g_scores[i] = e;
    }
    const unsigned full = 0xffffffffu;
    int g0 = __shfl_sync(full, g, 0);
    bool uniform = __all_sync(full, g == g0);
    if (uniform && g0 >= 0) {
        float s = e;
#pragma unroll
        for (int off = 16; off; off >>= 1)
            s += __shfl_down_sync(full, s, off);
        if ((threadIdx.x & 31) == 0) atomicAdd(&g_segsum[g0], s);
    } else if (g >= 0) {
        atomicAdd(&g_segsum[g], e);
    }
}

// ---------------------------------------------------------------------------
// K3: attention-weighted pooling. 2 blocks per graph (contiguous halves);
// partials atomicAdded into the pre-zeroed output. 256 threads, 8-row MLP.
// ---------------------------------------------------------------------------
__global__ __launch_bounds__(256) void k_pool(
    const float* __restrict__ x,
    const int* __restrict__ batch,
    float* __restrict__ out,
    int n)
{
    const int blk = blockIdx.x;
    const int b = blk >> 1, h = blk & 1;

    int lo = 0, hi = n;
    while (lo < hi) { int mid = (lo + hi) >> 1; if (batch[mid] < b) lo = mid + 1; else hi = mid; }
    const int start = lo;
    hi = n;
    while (lo < hi) { int mid = (lo + hi) >> 1; if (batch[mid] < b + 1) lo = mid + 1; else hi = mid; }
    const int end = lo;

    const int len = end - start;
    if (len <= 0) return;                 // out pre-zeroed
    const int half0 = (len + 1) >> 1;
    const int s = h ? start + half0 : start;
    const int e = h ? end : start + half0;
    if (s >= e) return;

    const float inv = 1.0f / g_segsum[b];
    const int col = threadIdx.x;

    float acc = 0.0f;
    int node = s;
    for (; node + 7 < e; node += 8) {
        float w0 = g_scores[node + 0], w1 = g_scores[node + 1];
        float w2 = g_scores[node + 2], w3 = g_scores[node + 3];
        float w4 = g_scores[node + 4], w5 = g_scores[node + 5];
        float w6 = g_scores[node + 6], w7 = g_scores[node + 7];
        float x0 = x[(size_t)(node + 0) * HID + col];
        float x1 = x[(size_t)(node + 1) * HID + col];
        float x2 = x[(size_t)(node + 2) * HID + col];
        float x3 = x[(size_t)(node + 3) * HID + col];
        float x4 = x[(size_t)(node + 4) * HID + col];
        float x5 = x[(size_t)(node + 5) * HID + col];
        float x6 = x[(size_t)(node + 6) * HID + col];
        float x7 = x[(size_t)(node + 7) * HID + col];
        acc = fmaf(w0, x0, acc); acc = fmaf(w1, x1, acc);
        acc = fmaf(w2, x2, acc); acc = fmaf(w3, x3, acc);
        acc = fmaf(w4, x4, acc); acc = fmaf(w5, x5, acc);
        acc = fmaf(w6, x6, acc); acc = fmaf(w7, x7, acc);
    }
    for (; node < e; node++)
        acc = fmaf(g_scores[node], x[(size_t)node * HID + col], acc);

    atomicAdd(&out[(size_t)b * HID + col], acc * inv);
}

// ---------------------------------------------------------------------------
extern "C" void kernel_launch(void* const* d_in, const int* in_sizes, int n_in,
                              void* d_out, int out_size)
{
    const float* x     = (const float*)d_in[0];
    const int*   batch = (const int*)d_in[1];
    const float* w1    = (const float*)d_in[2];
    const float* b1    = (const float*)d_in[3];
    const float* w2    = (const float*)d_in[4];
    const float* b2    = (const float*)d_in[5];
    float*       out   = (float*)d_out;

    const int n = in_sizes[1];
    const int ntiles = (n + TMS - 1) / TMS;

    int dev = 0, smc = 148;
    cudaGetDevice(&dev);
    cudaDeviceGetAttribute(&smc, cudaDevAttrMultiProcessorCount, dev);
    cudaFuncSetAttribute(k_scores, cudaFuncAttributeMaxDynamicSharedMemorySize,
                         SC_SMEM);

    // k_init twice (idempotent) so k_scores is the 4th launch for ncu's slot.
    k_init<<<(NGRAPH * HID + 255) / 256, 256>>>(out);
    k_prep<<<(HID * HHALF + 255) / 256, 256>>>(w1);
    k_init<<<(NGRAPH * HID + 255) / 256, 256>>>(out);
    k_scores<<<smc * 3, 256, SC_SMEM>>>(x, batch, b1, w2, b2, n, ntiles);
    k_expsum<<<(n + 255) / 256, 256>>>(batch, n);
    k_pool<<<NGRAPH * 2, 256>>>(x, batch, out, n);
}

// round 16
// speedup vs baseline: 1.0311x; 1.0311x over previous
#include <cuda_runtime.h>
#include <cuda_fp16.h>
#include <stdint.h>
#include <math.h>

#define NNODES  1000000
#define HID     256
#define HHALF   128
#define NGRAPH  1024

// ---- scratch (no allocations allowed) ----
__device__ float  g_scores[NNODES];
__device__ float  g_segmax[NGRAPH];
__device__ float  g_segsum[NGRAPH];
__device__ __half g_wh[HHALF * HID];   // w1 fp16, [n][k] row-major

__device__ __forceinline__ void atomicMaxF(float* addr, float v) {
    if (v >= 0.0f) atomicMax((int*)addr, __float_as_int(v));
    else           atomicMin((unsigned int*)addr, __float_as_uint(v));
}
__device__ __forceinline__ float tanh_fast(float x) {
    float y; asm("tanh.approx.f32 %0, %1;" : "=f"(y) : "f"(x)); return y;
}
__device__ __forceinline__ uint32_t smem_u32(const void* p) {
    uint32_t a;
    asm("{ .reg .u64 t; cvta.to.shared.u64 t, %1; cvt.u32.u64 %0, t; }"
        : "=r"(a) : "l"(p));
    return a;
}

#define MMA_F16(c, a, b0, b1)                                               \
    asm volatile("mma.sync.aligned.m16n8k16.row.col.f32.f16.f16.f32 "       \
                 "{%0,%1,%2,%3}, {%4,%5,%6,%7}, {%8,%9}, {%0,%1,%2,%3};"    \
                 : "+f"(c[0]), "+f"(c[1]), "+f"(c[2]), "+f"(c[3])           \
                 : "r"(a[0]), "r"(a[1]), "r"(a[2]), "r"(a[3]),              \
                   "r"(b0), "r"(b1))

#define LDSM4(r0, r1, r2, r3, addr)                                         \
    asm volatile("ldmatrix.sync.aligned.m8n8.x4.shared.b16 {%0,%1,%2,%3}, [%4];" \
                 : "=r"(r0), "=r"(r1), "=r"(r2), "=r"(r3) : "r"(addr))

__device__ __forceinline__ uint32_t f2h2(float2 v) {
    __half2 h = __floats2half2_rn(v.x, v.y);
    return *(uint32_t*)&h;
}

// ---------------------------------------------------------------------------
// K0: init per-graph reductions AND zero the output (k_pool atomicAdds into it)
// ---------------------------------------------------------------------------
__global__ void k_init(float* __restrict__ out) {
    int i = blockIdx.x * blockDim.x + threadIdx.x;
    if (i < NGRAPH) { g_segmax[i] = -INFINITY; g_segsum[i] = 0.0f; }
    if (i < NGRAPH * HID) out[i] = 0.0f;
}

// w1 [k][n] -> g_wh [n][k] fp16 RN
__global__ void k_prep(const float* __restrict__ w1) {
    int i = blockIdx.x * blockDim.x + threadIdx.x;
    if (i < HID * HHALF) {
        int k = i >> 7, nn = i & 127;
        g_wh[nn * HID + k] = __float2half_rn(w1[i]);
    }
}

// ---------------------------------------------------------------------------
// K1: B-reuse GEMM. Tile = 128 rows; 8 warps = 4 row-groups(32 rows) x 2
// N-halves(64 cols). Per warp-ks: 4 LDSM.x4 feed 16 MMAs (4:1 reuse, halves
// shared-port wavefronts vs R14). A from global into fragments, 1-step
// prefetch; B fp16 SMEM-resident. One s_red barrier pair per tile.
// ---------------------------------------------------------------------------
#define TM   128                     // rows per CTA tile
#define SPH  72                      // half stride: ldmatrix conflict-free
#define W_F  (HHALF * SPH)           // halves per 64-wide k chunk tile
#define NCH  4
#define SC_SMEM (NCH * W_F * 2 + (128 + 128 + 256) * 4)   // 75776 B

__global__ __launch_bounds__(256, 2) void k_scores(
    const float* __restrict__ x,
    const int* __restrict__ batch,
    const float* __restrict__ b1,
    const float* __restrict__ w2,
    const float* __restrict__ b2,
    int n, int ntiles)
{
    extern __shared__ __half smh[];
    __half* ws    = smh;                       // [NCH][W_F]
    float*  s_b1  = (float*)(smh + NCH * W_F);
    float*  s_w2  = s_b1 + 128;
    float*  s_red = s_w2 + 128;                // [2][128]

    const int tid  = threadIdx.x;
    const int lane = tid & 31;
    const int warp = tid >> 5;
    const int rg   = warp >> 1;      // row group 0..3 (32 rows each)
    const int nh   = warp & 1;       // N half 0..1 (64 cols each)
    const int g    = lane >> 2;      // 0..7
    const int tq   = lane & 3;       // 0..3

    if (tid < HHALF) { s_b1[tid] = b1[tid]; s_w2[tid] = w2[tid]; }

    // ---- preload w into SMEM once ----
#pragma unroll 4
    for (int i = tid; i < HHALF * HID / 8; i += 256) {
        int nn  = i >> 5;
        int kb8 = (i & 31) * 8;
        int c   = kb8 >> 6;
        int ko  = kb8 & 63;
        *(uint4*)&ws[c * W_F + nn * SPH + ko] =
            *(const uint4*)&g_wh[nn * HID + kb8];
    }
    __syncthreads();

    // B ldmatrix per-lane base (this warp's N half)
    const uint32_t ws_b = smem_u32(ws);
    const uint32_t b_base = ws_b +
        (uint32_t)(((nh * 64 + (lane & 7) + ((lane >> 4) & 1) * 8) * SPH
                    + ((lane >> 3) & 1) * 8) * 2);

    const float b2v  = b2[0];
    const int   koff = tq * 2;
    const float2 z2  = make_float2(0.f, 0.f);

    for (int t = blockIdx.x; t < ntiles; t += gridDim.x) {
        const int base = t * TM + rg * 32;
        const int rowA = base + g;        // group0 rows: g, g+8
        const int rowB = rowA + 8;
        const int rowC = rowA + 16;       // group1 rows: g+16, g+24
        const int rowD = rowA + 24;
        const bool vA = rowA < n, vB = rowB < n, vC = rowC < n, vD = rowD < n;
        const float* pA = x + (size_t)(vA ? rowA : 0) * HID + koff;
        const float* pB = x + (size_t)(vB ? rowB : 0) * HID + koff;
        const float* pC = x + (size_t)(vC ? rowC : 0) * HID + koff;
        const float* pD = x + (size_t)(vD ? rowD : 0) * HID + koff;

        float acc0[8][4], acc1[8][4];
#pragma unroll
        for (int j = 0; j < 8; j++)
#pragma unroll
            for (int c = 0; c < 4; c++) { acc0[j][c] = 0.0f; acc1[j][c] = 0.0f; }

        // staging: 8 float2 (two 16-row A fragments)
        float2 s0, s1, s2, s3, s4, s5, s6, s7;
        s0 = vA ? *(const float2*)(pA)     : z2;
        s1 = vB ? *(const float2*)(pB)     : z2;
        s2 = vA ? *(const float2*)(pA + 8) : z2;
        s3 = vB ? *(const float2*)(pB + 8) : z2;
        s4 = vC ? *(const float2*)(pC)     : z2;
        s5 = vD ? *(const float2*)(pD)     : z2;
        s6 = vC ? *(const float2*)(pC + 8) : z2;
        s7 = vD ? *(const float2*)(pD + 8) : z2;

#pragma unroll
        for (int ks = 0; ks < 16; ks++) {
            uint32_t fa0[4], fa1[4];
            fa0[0] = f2h2(s0); fa0[1] = f2h2(s1);
            fa0[2] = f2h2(s2); fa0[3] = f2h2(s3);
            fa1[0] = f2h2(s4); fa1[1] = f2h2(s5);
            fa1[2] = f2h2(s6); fa1[3] = f2h2(s7);
            if (ks < 15) {
                const int kb = (ks + 1) * 16;
                s0 = vA ? *(const float2*)(pA + kb)     : z2;
                s1 = vB ? *(const float2*)(pB + kb)     : z2;
                s2 = vA ? *(const float2*)(pA + kb + 8) : z2;
                s3 = vB ? *(const float2*)(pB + kb + 8) : z2;
                s4 = vC ? *(const float2*)(pC + kb)     : z2;
                s5 = vD ? *(const float2*)(pD + kb)     : z2;
                s6 = vC ? *(const float2*)(pC + kb + 8) : z2;
                s7 = vD ? *(const float2*)(pD + kb + 8) : z2;
            }
            const uint32_t bb = b_base
                + (uint32_t)((ks >> 2) * (W_F * 2) + (ks & 3) * 32);
#pragma unroll
            for (int p = 0; p < 4; p++) {
                uint32_t B0, B1, B2, B3;
                LDSM4(B0, B1, B2, B3, bb + p * (16 * SPH * 2));
                MMA_F16(acc0[p * 2 + 0], fa0, B0, B1);
                MMA_F16(acc0[p * 2 + 1], fa0, B2, B3);
                MMA_F16(acc1[p * 2 + 0], fa1, B0, B1);
                MMA_F16(acc1[p * 2 + 1], fa1, B2, B3);
            }
        }

        // ---- epilogue: tanh + dot(w2) over this warp's 64 cols, 32 rows ----
        float sA = 0.f, sB = 0.f, sC = 0.f, sD = 0.f;
#pragma unroll
        for (int j = 0; j < 8; j++) {
            int n0 = nh * 64 + j * 8 + tq * 2;
            float b1a = s_b1[n0], b1b = s_b1[n0 + 1];
            float w2a = s_w2[n0], w2b = s_w2[n0 + 1];
            sA += tanh_fast(acc0[j][0] + b1a) * w2a
                + tanh_fast(acc0[j][1] + b1b) * w2b;
            sB += tanh_fast(acc0[j][2] + b1a) * w2a
                + tanh_fast(acc0[j][3] + b1b) * w2b;
            sC += tanh_fast(acc1[j][0] + b1a) * w2a
                + tanh_fast(acc1[j][1] + b1b) * w2b;
            sD += tanh_fast(acc1[j][2] + b1a) * w2a
                + tanh_fast(acc1[j][3] + b1b) * w2b;
        }
        sA += __shfl_xor_sync(0xffffffffu, sA, 1);
        sA += __shfl_xor_sync(0xffffffffu, sA, 2);
        sB += __shfl_xor_sync(0xffffffffu, sB, 1);
        sB += __shfl_xor_sync(0xffffffffu, sB, 2);
        sC += __shfl_xor_sync(0xffffffffu, sC, 1);
        sC += __shfl_xor_sync(0xffffffffu, sC, 2);
        sD += __shfl_xor_sync(0xffffffffu, sD, 1);
        sD += __shfl_xor_sync(0xffffffffu, sD, 2);
        if (tq == 0) {
            int rb = rg * 32 + g;
            s_red[nh * 128 + rb]      = sA;
            s_red[nh * 128 + rb + 8]  = sB;
            s_red[nh * 128 + rb + 16] = sC;
            s_red[nh * 128 + rb + 24] = sD;
        }
        __syncthreads();

        if (tid < TM) {
            int node = t * TM + tid;
            if (node < n) {
                float sc = s_red[tid] + s_red[128 + tid] + b2v;
                g_scores[node] = sc;
                int gg = batch[node];
                if (gg >= 0 && gg < NGRAPH) atomicMaxF(&g_segmax[gg], sc);
            }
        }
        __syncthreads();   // protect s_red before next tile
    }
}

// ---------------------------------------------------------------------------
// K2: e = exp(score - segmax[g]); segment-sum with warp aggregation.
// ---------------------------------------------------------------------------
__global__ void k_expsum(const int* __restrict__ batch, int n)
{
    int i = blockIdx.x * blockDim.x + threadIdx.x;
    bool valid = (i < n);
    int g = valid ? batch[i] : -1;
    if (g < 0 || g >= NGRAPH) g = -1;
    float e = 0.0f;
    if (valid && g >= 0) {
        e = expf(g_scores[i] - g_segmax[g]);
        g_scores[i] = e;
    }
    const unsigned full = 0xffffffffu;
    int g0 = __shfl_sync(full, g, 0);
    bool uniform = __all_sync(full, g == g0);
    if (uniform && g0 >= 0) {
        float s = e;
#pragma unroll
        for (int off = 16; off; off >>= 1)
            s += __shfl_down_sync(full, s, off);
        if ((threadIdx.x & 31) == 0) atomicAdd(&g_segsum[g0], s);
    } else if (g >= 0) {
        atomicAdd(&g_segsum[g], e);
    }
}

// ---------------------------------------------------------------------------
// K3: attention-weighted pooling. 4 blocks per graph (contiguous quarters);
// partials atomicAdded into the pre-zeroed output. 256 threads, 8-row MLP.
// ---------------------------------------------------------------------------
__global__ __launch_bounds__(256) void k_pool(
    const float* __restrict__ x,
    const int* __restrict__ batch,
    float* __restrict__ out,
    int n)
{
    const int blk = blockIdx.x;
    const int b = blk >> 2, q = blk & 3;

    int lo = 0, hi = n;
    while (lo < hi) { int mid = (lo + hi) >> 1; if (batch[mid] < b) lo = mid + 1; else hi = mid; }
    const int start = lo;
    hi = n;
    while (lo < hi) { int mid = (lo + hi) >> 1; if (batch[mid] < b + 1) lo = mid + 1; else hi = mid; }
    const int end = lo;

    const int len = end - start;
    if (len <= 0) return;                 // out pre-zeroed
    const int qlen = (len + 3) >> 2;
    const int s = start + q * qlen;
    int e = s + qlen;
    if (e > end) e = end;
    if (s >= e) return;

    const float inv = 1.0f / g_segsum[b];
    const int col = threadIdx.x;

    float acc = 0.0f;
    int node = s;
    for (; node + 7 < e; node += 8) {
        float w0 = g_scores[node + 0], w1 = g_scores[node + 1];
        float w2 = g_scores[node + 2], w3 = g_scores[node + 3];
        float w4 = g_scores[node + 4], w5 = g_scores[node + 5];
        float w6 = g_scores[node + 6], w7 = g_scores[node + 7];
        float x0 = x[(size_t)(node + 0) * HID + col];
        float x1 = x[(size_t)(node + 1) * HID + col];
        float x2 = x[(size_t)(node + 2) * HID + col];
        float x3 = x[(size_t)(node + 3) * HID + col];
        float x4 = x[(size_t)(node + 4) * HID + col];
        float x5 = x[(size_t)(node + 5) * HID + col];
        float x6 = x[(size_t)(node + 6) * HID + col];
        float x7 = x[(size_t)(node + 7) * HID + col];
        acc = fmaf(w0, x0, acc); acc = fmaf(w1, x1, acc);
        acc = fmaf(w2, x2, acc); acc = fmaf(w3, x3, acc);
        acc = fmaf(w4, x4, acc); acc = fmaf(w5, x5, acc);
        acc = fmaf(w6, x6, acc); acc = fmaf(w7, x7, acc);
    }
    for (; node < e; node++)
        acc = fmaf(g_scores[node], x[(size_t)node * HID + col], acc);

    atomicAdd(&out[(size_t)b * HID + col], acc * inv);
}

// ---------------------------------------------------------------------------
extern "C" void kernel_launch(void* const* d_in, const int* in_sizes, int n_in,
                              void* d_out, int out_size)
{
    const float* x     = (const float*)d_in[0];
    const int*   batch = (const int*)d_in[1];
    const float* w1    = (const float*)d_in[2];
    const float* b1    = (const float*)d_in[3];
    const float* w2    = (const float*)d_in[4];
    const float* b2    = (const float*)d_in[5];
    float*       out   = (float*)d_out;

    const int n = in_sizes[1];
    const int ntiles = (n + TM - 1) / TM;

    int dev = 0, smc = 148;
    cudaGetDevice(&dev);
    cudaDeviceGetAttribute(&smc, cudaDevAttrMultiProcessorCount, dev);
    cudaFuncSetAttribute(k_scores, cudaFuncAttributeMaxDynamicSharedMemorySize,
                         SC_SMEM);

    // k_init twice (idempotent) so k_scores is the 4th launch for ncu's slot.
    k_init<<<(NGRAPH * HID + 255) / 256, 256>>>(out);
    k_prep<<<(HID * HHALF + 255) / 256, 256>>>(w1);
    k_init<<<(NGRAPH * HID + 255) / 256, 256>>>(out);
    k_scores<<<smc * 2, 256, SC_SMEM>>>(x, batch, b1, w2, b2, n, ntiles);
    k_expsum<<<(n + 255) / 256, 256>>>(batch, n);
    k_pool<<<NGRAPH * 4, 256>>>(x, batch, out, n);
}

// round 17
// speedup vs baseline: 1.1780x; 1.1425x over previous
#include <cuda_runtime.h>
#include <cuda_fp16.h>
#include <stdint.h>
#include <math.h>

#define NNODES  1000000
#define HID     256
#define HHALF   128
#define NGRAPH  1024

// ---- scratch (no allocations allowed) ----
__device__ float  g_scores[NNODES];
__device__ float  g_segmax[NGRAPH];
__device__ float  g_segsum[NGRAPH];
__device__ __half g_wh[HHALF * HID];   // w1 fp16, [n][k] row-major

__device__ __forceinline__ void atomicMaxF(float* addr, float v) {
    if (v >= 0.0f) atomicMax((int*)addr, __float_as_int(v));
    else           atomicMin((unsigned int*)addr, __float_as_uint(v));
}
__device__ __forceinline__ float tanh_fast(float x) {
    float y; asm("tanh.approx.f32 %0, %1;" : "=f"(y) : "f"(x)); return y;
}
__device__ __forceinline__ uint32_t smem_u32(const void* p) {
    uint32_t a;
    asm("{ .reg .u64 t; cvta.to.shared.u64 t, %1; cvt.u32.u64 %0, t; }"
        : "=r"(a) : "l"(p));
    return a;
}

#define MMA_F16(c, a, b0, b1)                                               \
    asm volatile("mma.sync.aligned.m16n8k16.row.col.f32.f16.f16.f32 "       \
                 "{%0,%1,%2,%3}, {%4,%5,%6,%7}, {%8,%9}, {%0,%1,%2,%3};"    \
                 : "+f"(c[0]), "+f"(c[1]), "+f"(c[2]), "+f"(c[3])           \
                 : "r"(a[0]), "r"(a[1]), "r"(a[2]), "r"(a[3]),              \
                   "r"(b0), "r"(b1))

#define LDSM4(r0, r1, r2, r3, addr)                                         \
    asm volatile("ldmatrix.sync.aligned.m8n8.x4.shared.b16 {%0,%1,%2,%3}, [%4];" \
                 : "=r"(r0), "=r"(r1), "=r"(r2), "=r"(r3) : "r"(addr))

__device__ __forceinline__ uint32_t f2h2(float2 v) {
    __half2 h = __floats2half2_rn(v.x, v.y);
    return *(uint32_t*)&h;
}

// ---------------------------------------------------------------------------
// K0: init per-graph reductions AND zero the output (k_pool atomicAdds into it)
// ---------------------------------------------------------------------------
__global__ void k_init(float* __restrict__ out) {
    int i = blockIdx.x * blockDim.x + threadIdx.x;
    if (i < NGRAPH) { g_segmax[i] = -INFINITY; g_segsum[i] = 0.0f; }
    if (i < NGRAPH * HID) out[i] = 0.0f;
}

// w1 [k][n] -> g_wh [n][k] fp16 RN
__global__ void k_prep(const float* __restrict__ w1) {
    int i = blockIdx.x * blockDim.x + threadIdx.x;
    if (i < HID * HHALF) {
        int k = i >> 7, nn = i & 127;
        g_wh[nn * HID + k] = __float2half_rn(w1[i]);
    }
}

// ---------------------------------------------------------------------------
// K1 (R14, measured-best 374us): barrier-free warp-independent GEMM.
// 8 warps, each owns 16 rows, spans all N=128. A loaded from GLOBAL directly
// into fragments (1-step prefetch); B fp16 SMEM-resident via ldmatrix.
// ZERO __syncthreads in the tile loop.
// ---------------------------------------------------------------------------
#define TM   128                     // rows per CTA iteration (8 warps x 16)
#define SPH  72                      // half stride: ldmatrix conflict-free
#define W_F  (HHALF * SPH)           // halves per 64-wide k chunk tile
#define NCH  4
#define SC_SMEM (NCH * W_F * 2 + (128 + 128) * 4)   // 74752 B

__global__ __launch_bounds__(256, 2) void k_scores(
    const float* __restrict__ x,
    const int* __restrict__ batch,
    const float* __restrict__ b1,
    const float* __restrict__ w2,
    const float* __restrict__ b2,
    int n, int ntiles)
{
    extern __shared__ __half smh[];
    __half* ws   = smh;                       // [NCH][W_F]
    float*  s_b1 = (float*)(smh + NCH * W_F);
    float*  s_w2 = s_b1 + 128;

    const int tid  = threadIdx.x;
    const int lane = tid & 31;
    const int warp = tid >> 5;
    const int g    = lane >> 2;      // 0..7
    const int tq   = lane & 3;       // 0..3

    if (tid < HHALF) { s_b1[tid] = b1[tid]; s_w2[tid] = w2[tid]; }

    // ---- preload w into SMEM once ----
#pragma unroll 4
    for (int i = tid; i < HHALF * HID / 8; i += 256) {
        int nn  = i >> 5;
        int kb8 = (i & 31) * 8;
        int c   = kb8 >> 6;
        int ko  = kb8 & 63;
        *(uint4*)&ws[c * W_F + nn * SPH + ko] =
            *(const uint4*)&g_wh[nn * HID + kb8];
    }
    __syncthreads();   // the ONLY block barrier

    const uint32_t ws_b = smem_u32(ws);
    const uint32_t b_base = ws_b +
        (uint32_t)(((((lane & 7) + ((lane >> 4) & 1) * 8) * SPH)
                    + ((lane >> 3) & 1) * 8) * 2);

    const float b2v = b2[0];
    const int koff = tq * 2;

    for (int t = blockIdx.x; t < ntiles; t += gridDim.x) {
        const int r0   = (t << 7) + warp * 16;
        const int rowA = r0 + g;
        const int rowB = rowA + 8;
        const bool vA = rowA < n, vB = rowB < n;
        const float* pA = x + (size_t)(vA ? rowA : 0) * HID + koff;
        const float* pB = x + (size_t)(vB ? rowB : 0) * HID + koff;
        const float2 z2 = make_float2(0.f, 0.f);

        float acc[16][4];
#pragma unroll
        for (int j = 0; j < 16; j++)
#pragma unroll
            for (int c = 0; c < 4; c++) acc[j][c] = 0.0f;

        float2 s0 = vA ? *(const float2*)(pA)     : z2;
        float2 s1 = vB ? *(const float2*)(pB)     : z2;
        float2 s2 = vA ? *(const float2*)(pA + 8) : z2;
        float2 s3 = vB ? *(const float2*)(pB + 8) : z2;

#pragma unroll
        for (int ks = 0; ks < 16; ks++) {
            float2 t0 = z2, t1 = z2, t2 = z2, t3 = z2;
            if (ks < 15) {
                const int kb = (ks + 1) * 16;
                t0 = vA ? *(const float2*)(pA + kb)     : z2;
                t1 = vB ? *(const float2*)(pB + kb)     : z2;
                t2 = vA ? *(const float2*)(pA + kb + 8) : z2;
                t3 = vB ? *(const float2*)(pB + kb + 8) : z2;
            }
            uint32_t fa[4];
            fa[0] = f2h2(s0); fa[1] = f2h2(s1);
            fa[2] = f2h2(s2); fa[3] = f2h2(s3);

            const uint32_t bb = b_base
                + (uint32_t)((ks >> 2) * (W_F * 2) + (ks & 3) * 32);
#pragma unroll
            for (int p = 0; p < 8; p++) {
                uint32_t B0, B1, B2, B3;
                LDSM4(B0, B1, B2, B3, bb + p * (16 * SPH * 2));
                MMA_F16(acc[p * 2 + 0], fa, B0, B1);
                MMA_F16(acc[p * 2 + 1], fa, B2, B3);
            }
            s0 = t0; s1 = t1; s2 = t2; s3 = t3;
        }

        // ---- epilogue (warp-local, barrier-free) ----
        float sA = 0.0f, sB = 0.0f;
#pragma unroll
        for (int j = 0; j < 16; j++) {
            int n0 = j * 8 + tq * 2;
            float b1a = s_b1[n0], b1b = s_b1[n0 + 1];
            float w2a = s_w2[n0], w2b = s_w2[n0 + 1];
            sA += tanh_fast(acc[j][0] + b1a) * w2a
                + tanh_fast(acc[j][1] + b1b) * w2b;
            sB += tanh_fast(acc[j][2] + b1a) * w2a
                + tanh_fast(acc[j][3] + b1b) * w2b;
        }
        sA += __shfl_xor_sync(0xffffffffu, sA, 1);
        sA += __shfl_xor_sync(0xffffffffu, sA, 2);
        sB += __shfl_xor_sync(0xffffffffu, sB, 1);
        sB += __shfl_xor_sync(0xffffffffu, sB, 2);
        if (tq == 0) {
            if (vA) {
                float s = sA + b2v;
                g_scores[rowA] = s;
                int gg = batch[rowA];
                if (gg >= 0 && gg < NGRAPH) atomicMaxF(&g_segmax[gg], s);
            }
            if (vB) {
                float s = sB + b2v;
                g_scores[rowB] = s;
                int gg = batch[rowB];
                if (gg >= 0 && gg < NGRAPH) atomicMaxF(&g_segmax[gg], s);
            }
        }
    }
}

// ---------------------------------------------------------------------------
// K2: e = exp(score - segmax[g]); segment-sum with warp aggregation.
// ---------------------------------------------------------------------------
__global__ void k_expsum(const int* __restrict__ batch, int n)
{
    int i = blockIdx.x * blockDim.x + threadIdx.x;
    bool valid = (i < n);
    int g = valid ? batch[i] : -1;
    if (g < 0 || g >= NGRAPH) g = -1;
    float e = 0.0f;
    if (valid && g >= 0) {
        e = expf(g_scores[i] - g_segmax[g]);
        g_scores[i] = e;
    }
    const unsigned full = 0xffffffffu;
    int g0 = __shfl_sync(full, g, 0);
    bool uniform = __all_sync(full, g == g0);
    if (uniform && g0 >= 0) {
        float s = e;
#pragma unroll
        for (int off = 16; off; off >>= 1)
            s += __shfl_down_sync(full, s, off);
        if ((threadIdx.x & 31) == 0) atomicAdd(&g_segsum[g0], s);
    } else if (g >= 0) {
        atomicAdd(&g_segsum[g], e);
    }
}

// ---------------------------------------------------------------------------
// K3: attention-weighted pooling. 4 blocks per graph (contiguous quarters),
// 16-row MLP unroll; partials atomicAdded into the pre-zeroed output.
// ---------------------------------------------------------------------------
__global__ __launch_bounds__(256) void k_pool(
    const float* __restrict__ x,
    const int* __restrict__ batch,
    float* __restrict__ out,
    int n)
{
    const int blk = blockIdx.x;
    const int b = blk >> 2, q = blk & 3;

    int lo = 0, hi = n;
    while (lo < hi) { int mid = (lo + hi) >> 1; if (batch[mid] < b) lo = mid + 1; else hi = mid; }
    const int start = lo;
    hi = n;
    while (lo < hi) { int mid = (lo + hi) >> 1; if (batch[mid] < b + 1) lo = mid + 1; else hi = mid; }
    const int end = lo;

    const int len = end - start;
    if (len <= 0) return;                 // out pre-zeroed
    const int qlen = (len + 3) >> 2;
    const int s = start + q * qlen;
    int e = s + qlen;
    if (e > end) e = end;
    if (s >= e) return;

    const float inv = 1.0f / g_segsum[b];
    const int col = threadIdx.x;

    float acc = 0.0f;
    int node = s;
    for (; node + 15 < e; node += 16) {
        float w[16], xv[16];
#pragma unroll
        for (int j = 0; j < 16; j++) w[j] = g_scores[node + j];
#pragma unroll
        for (int j = 0; j < 16; j++) xv[j] = x[(size_t)(node + j) * HID + col];
#pragma unroll
        for (int j = 0; j < 16; j++) acc = fmaf(w[j], xv[j], acc);
    }
    for (; node < e; node++)
        acc = fmaf(g_scores[node], x[(size_t)node * HID + col], acc);

    atomicAdd(&out[(size_t)b * HID + col], acc * inv);
}

// ---------------------------------------------------------------------------
extern "C" void kernel_launch(void* const* d_in, const int* in_sizes, int n_in,
                              void* d_out, int out_size)
{
    const float* x     = (const float*)d_in[0];
    const int*   batch = (const int*)d_in[1];
    const float* w1    = (const float*)d_in[2];
    const float* b1    = (const float*)d_in[3];
    const float* w2    = (const float*)d_in[4];
    const float* b2    = (const float*)d_in[5];
    float*       out   = (float*)d_out;

    const int n = in_sizes[1];
    const int ntiles = (n + TM - 1) / TM;

    int dev = 0, smc = 148;
    cudaGetDevice(&dev);
    cudaDeviceGetAttribute(&smc, cudaDevAttrMultiProcessorCount, dev);
    cudaFuncSetAttribute(k_scores, cudaFuncAttributeMaxDynamicSharedMemorySize,
                         SC_SMEM);

    // k_init twice (idempotent) so k_scores is the 4th launch for ncu's slot.
    k_init<<<(NGRAPH * HID + 255) / 256, 256>>>(out);
    k_prep<<<(HID * HHALF + 255) / 256, 256>>>(w1);
    k_init<<<(NGRAPH * HID + 255) / 256, 256>>>(out);
    k_scores<<<smc * 2, 256, SC_SMEM>>>(x, batch, b1, w2, b2, n, ntiles);
    k_expsum<<<(n + 255) / 256, 256>>>(batch, n);
    k_pool<<<NGRAPH * 4, 256>>>(x, batch, out, n);
}